// round 5
// baseline (speedup 1.0000x reference)
#include <cuda_runtime.h>
#include <math.h>

#define NB 16
#define HH 32
#define WW 32
#define TT 16
#define VV 64
#define PP (HH*WW)          // 1024
#define LRELU_ALPHA 0.2f

typedef unsigned long long ull;

// ---------------- f32x2 helpers --------------------------------------------
__device__ __forceinline__ ull pk2(float lo, float hi) {
    ull r; asm("mov.b64 %0, {%1, %2};" : "=l"(r) : "f"(lo), "f"(hi)); return r;
}
__device__ __forceinline__ void upk2(ull x, float& lo, float& hi) {
    asm("mov.b64 {%0, %1}, %2;" : "=f"(lo), "=f"(hi) : "l"(x));
}
__device__ __forceinline__ ull ffma2(ull a, ull b, ull c) {
    ull d; asm("fma.rn.f32x2 %0, %1, %2, %3;" : "=l"(d) : "l"(a), "l"(b), "l"(c)); return d;
}

// ---------------- scratch (device globals; no runtime allocation) ----------
__device__ float g_Wt[(size_t)NB*TT*PP*VV];   // [n][t][p][v]  64 MB
__device__ float g_Ei[NB*VV*TT];
__device__ float g_Ej[NB*VV*TT];
__device__ float g_att[NB*TT*VV*VV];          // [n][t][i][j]  4 MB
__device__ float g_adjn[VV*VV];
__device__ float g_M[NB*TT*VV*VV];            // [n][t][j][v]  4 MB

// ---------------- 1) 3x3 SAME conv, packed over `to` pairs -----------------
// Wh[n,v,y,x,to] = b[to] + sum_{dy,dx,ti} h[n,y+dy-1,x+dx-1,ti,v]*w[dy,dx,ti,to]
// write to g_Wt[n][to][p][v]
__global__ void __launch_bounds__(128) k_conv(const float* __restrict__ h,
                                              const float* __restrict__ cw,
                                              const float* __restrict__ cb) {
    __shared__ __align__(16) float sw[9*TT*TT];   // 2304 floats, [tap][ti][to]
    __shared__ float sb[TT];
    for (int i = threadIdx.x; i < 9*TT*TT; i += 128) sw[i] = cw[i];
    if (threadIdx.x < TT) sb[threadIdx.x] = cb[threadIdx.x];
    __syncthreads();

    const int v = threadIdx.x & 63;
    const int x = (blockIdx.x << 1) | (threadIdx.x >> 6);
    const int y = blockIdx.y;
    const int n = blockIdx.z;

    ull acc[8];                      // pairs over to: (2q, 2q+1)
#pragma unroll
    for (int q = 0; q < 8; q++) acc[q] = pk2(sb[2*q], sb[2*q+1]);

    for (int dy = 0; dy < 3; dy++) {
        const int yy = y + dy - 1;
        if (yy < 0 || yy >= HH) continue;
        for (int dx = 0; dx < 3; dx++) {
            const int xx = x + dx - 1;
            if (xx < 0 || xx >= WW) continue;
            const float* hp = h + ((size_t)((n*HH + yy)*WW + xx) * TT) * VV + v;
            const float* wp = sw + (dy*3 + dx) * TT * TT;
#pragma unroll
            for (int ti = 0; ti < TT; ti++) {
                const float hv = hp[ti * VV];
                const ull hv2 = pk2(hv, hv);
                const ulonglong2* w2p = reinterpret_cast<const ulonglong2*>(wp + ti*TT);
#pragma unroll
                for (int q = 0; q < 4; q++) {
                    const ulonglong2 w2 = w2p[q];      // 4 to-values = 2 pairs
                    acc[2*q]   = ffma2(hv2, w2.x, acc[2*q]);
                    acc[2*q+1] = ffma2(hv2, w2.y, acc[2*q+1]);
                }
            }
        }
    }
    const int p = y*WW + x;
#pragma unroll
    for (int q = 0; q < 8; q++) {
        float lo, hi; upk2(acc[q], lo, hi);
        g_Wt[((size_t)(n*TT + 2*q)   * PP + p) * VV + v] = lo;
        g_Wt[((size_t)(n*TT + 2*q+1) * PP + p) * VV + v] = hi;
    }
}

// ---------------- 2) Ei / Ej reductions ------------------------------------
__global__ void __launch_bounds__(256) k_eij(const float* __restrict__ a) {
    __shared__ float sa[2*HH*WW];          // 2048
    __shared__ float red[2][4][VV];
    for (int i = threadIdx.x; i < 2*HH*WW; i += 256) sa[i] = a[i];
    __syncthreads();

    const int v  = threadIdx.x & 63;
    const int q  = threadIdx.x >> 6;       // 0..3, splits t range
    const int tp = blockIdx.x;             // 0..15
    const int n  = blockIdx.y;

    float ei = 0.f, ej = 0.f;
    for (int t = q*4; t < q*4 + 4; t++) {
        const float* wt = g_Wt + ((size_t)(n*TT + t) * PP + 2*tp*WW) * VV + v;
#pragma unroll 8
        for (int rw = 0; rw < 64; rw++) {
            const float xv = wt[rw * VV];
            const int r = rw >> 5, w = rw & 31;
            ei += xv * sa[(r*64 + w)      * 16 + t];
            ej += xv * sa[(r*64 + 32 + w) * 16 + t];
        }
    }
    red[0][q][v] = ei; red[1][q][v] = ej;
    __syncthreads();
    if (q == 0) {
        float si = red[0][0][v] + red[0][1][v] + red[0][2][v] + red[0][3][v];
        float sj = red[1][0][v] + red[1][1][v] + red[1][2][v] + red[1][3][v];
        g_Ei[(n*VV + v)*TT + tp] = si;
        g_Ej[(n*VV + v)*TT + tp] = sj;
    }
}

// ---------------- 3) adjacency normalization (tiny, 1 block) ---------------
__global__ void __launch_bounds__(64) k_adj(const float* __restrict__ B) {
    __shared__ float smin[VV], smax[VV], sd[VV];
    __shared__ float s_amin, s_ascale;
    const int i = threadIdx.x;
    float mn = 1e30f, mx = -1e30f;
    for (int j = 0; j < VV; j++) {
        float val = B[i*VV + j] + (i == j ? 1.f : 0.f);
        mn = fminf(mn, val); mx = fmaxf(mx, val);
    }
    smin[i] = mn; smax[i] = mx;
    __syncthreads();
    if (i == 0) {
        float a = 1e30f, b = -1e30f;
        for (int j = 0; j < VV; j++) { a = fminf(a, smin[j]); b = fmaxf(b, smax[j]); }
        s_amin = a; s_ascale = 1.f / (b - a);
    }
    __syncthreads();
    const float amin = s_amin, asc = s_ascale;
    float rs = 0.f;
    for (int j = 0; j < VV; j++)
        rs += (B[i*VV + j] + (i == j ? 1.f : 0.f) - amin) * asc;
    sd[i] = 1.f / sqrtf(rs);
    __syncthreads();
    const float di = sd[i];
    for (int j = 0; j < VV; j++) {
        float val = (B[i*VV + j] + (i == j ? 1.f : 0.f) - amin) * asc;
        g_adjn[i*VV + j] = val * di * sd[j];
    }
}

// ---------------- 4) leaky-relu + softmax over T ---------------------------
// att[n][t][i][j] = softmax_t( lrelu(Ei[n,i,t] + Ej[n,j,t]) )
__global__ void __launch_bounds__(256) k_soft() {
    const int j  = threadIdx.x & 63;
    const int li = threadIdx.x >> 6;        // 0..3
    const int i  = blockIdx.x * 4 + li;
    const int n  = blockIdx.y;
    __shared__ float sEi[4][TT];
    if (j < TT) sEi[li][j] = g_Ei[(n*VV + i)*TT + j];
    __syncthreads();

    float e[TT];
    float mx = -1e30f;
#pragma unroll
    for (int t = 0; t < TT; t++) {
        float x = sEi[li][t] + g_Ej[(n*VV + j)*TT + t];
        x = (x > 0.f) ? x : LRELU_ALPHA * x;
        e[t] = x;
        mx = fmaxf(mx, x);
    }
    float s = 0.f;
#pragma unroll
    for (int t = 0; t < TT; t++) { e[t] = expf(e[t] - mx); s += e[t]; }
    const float inv = 1.f / s;
#pragma unroll
    for (int t = 0; t < TT; t++)
        g_att[((size_t)(n*TT + t)*VV + i)*VV + j] = e[t] * inv;
}

// ---------------- 5) M[n,t,j,v] = sum_i att[n,t,i,j] * adjn[i,v] -----------
__global__ void __launch_bounds__(256) k_M() {
    const int t = blockIdx.x, n = blockIdx.y;
    __shared__ float s_att[VV*VV];
    __shared__ float s_adj[VV*VV];
    const float* ap = g_att + (size_t)(n*TT + t) * VV * VV;
    for (int idx = threadIdx.x; idx < VV*VV; idx += 256) {
        s_att[idx] = ap[idx];
        s_adj[idx] = g_adjn[idx];
    }
    __syncthreads();
    const int v = threadIdx.x & 63, jg = threadIdx.x >> 6;
    float* mp = g_M + (size_t)(n*TT + t) * VV * VV;
    for (int j = jg*16; j < jg*16 + 16; j++) {
        float acc = 0.f;
#pragma unroll
        for (int i = 0; i < VV; i++)
            acc += s_att[i*VV + j] * s_adj[i*VV + v];
        mp[j*VV + v] = acc;
    }
}

// ---------------- 6) out[n,p,t,v] = elu( sum_j Wt[n,t,p,j] * M[n,t,j,v] ) --
// A operand stored in smem as duplicated f32x2 pairs; B pairs are natural.
// Row stride 66 (EVEN) so all ulonglong2 loads are 16-byte aligned.
__global__ void __launch_bounds__(256) k_out(float* __restrict__ out) {
    const int pt = blockIdx.x;          // 16 tiles of 64 p-rows
    const int t  = blockIdx.y;
    const int n  = blockIdx.z;
    __shared__ __align__(16) ull  sA2[64*66];    // [j][p] duplicated pairs, padded (even stride!)
    __shared__ __align__(16) float sM[64*64];    // [j][v]
    const float* wp = g_Wt + ((size_t)(n*TT + t) * PP + pt*64) * VV;
    const float* mp = g_M  + (size_t)(n*TT + t) * VV * VV;
    for (int idx = threadIdx.x; idx < 4096; idx += 256) {
        const int p = idx >> 6, j = idx & 63;
        const float w = wp[idx];
        sA2[j*66 + p] = pk2(w, w);      // transpose + duplicate
        sM[idx]       = mp[idx];
    }
    __syncthreads();

    const int tv = threadIdx.x & 15, tp = threadIdx.x >> 4;
    const int v0 = tv * 4, p0 = tp * 4;
    ull acc[4][2];
#pragma unroll
    for (int pi = 0; pi < 4; pi++) { acc[pi][0] = 0ull; acc[pi][1] = 0ull; }

#pragma unroll 4
    for (int j = 0; j < 64; j++) {
        const ulonglong2 a01 = *reinterpret_cast<const ulonglong2*>(&sA2[j*66 + p0]);
        const ulonglong2 a23 = *reinterpret_cast<const ulonglong2*>(&sA2[j*66 + p0 + 2]);
        const ulonglong2 b   = *reinterpret_cast<const ulonglong2*>(&sM[j*64 + v0]);
        acc[0][0] = ffma2(a01.x, b.x, acc[0][0]);
        acc[0][1] = ffma2(a01.x, b.y, acc[0][1]);
        acc[1][0] = ffma2(a01.y, b.x, acc[1][0]);
        acc[1][1] = ffma2(a01.y, b.y, acc[1][1]);
        acc[2][0] = ffma2(a23.x, b.x, acc[2][0]);
        acc[2][1] = ffma2(a23.x, b.y, acc[2][1]);
        acc[3][0] = ffma2(a23.y, b.x, acc[3][0]);
        acc[3][1] = ffma2(a23.y, b.y, acc[3][1]);
    }
#pragma unroll
    for (int pi = 0; pi < 4; pi++) {
        float x0, x1, x2, x3;
        upk2(acc[pi][0], x0, x1);
        upk2(acc[pi][1], x2, x3);
        float4 w4;
        w4.x = (x0 > 0.f) ? x0 : expm1f(x0);
        w4.y = (x1 > 0.f) ? x1 : expm1f(x1);
        w4.z = (x2 > 0.f) ? x2 : expm1f(x2);
        w4.w = (x3 > 0.f) ? x3 : expm1f(x3);
        *(float4*)(out + (((size_t)(n*PP + pt*64 + p0 + pi)) * TT + t) * VV + v0) = w4;
    }
}

// ---------------------------------------------------------------------------
extern "C" void kernel_launch(void* const* d_in, const int* in_sizes, int n_in,
                              void* d_out, int out_size) {
    const float* h  = (const float*)d_in[0];   // (16,32,32,16,64)
    const float* cw = (const float*)d_in[1];   // (3,3,16,16)
    const float* cb = (const float*)d_in[2];   // (16,)
    const float* a  = (const float*)d_in[3];   // (2048,1)
    const float* B  = (const float*)d_in[4];   // (64,64)
    float* out = (float*)d_out;

    k_conv<<<dim3(WW/2, HH, NB), 128>>>(h, cw, cb);
    k_adj<<<1, 64>>>(B);
    k_eij<<<dim3(TT, NB), 256>>>(a);
    k_soft<<<dim3(VV/4, NB), 256>>>();
    k_M<<<dim3(TT, NB), 256>>>();
    k_out<<<dim3(PP/64, TT, NB), 256>>>(out);
}

// round 9
// speedup vs baseline: 1.0679x; 1.0679x over previous
#include <cuda_runtime.h>
#include <cuda_bf16.h>
#include <math.h>
#include <stdint.h>

#define NB 16
#define HH 32
#define WW 32
#define TT 16
#define VV 64
#define PP (HH*WW)          // 1024
#define LRELU_ALPHA 0.2f

// ---------------- scratch (device globals; no runtime allocation) ----------
__device__ float g_Wt[(size_t)NB*TT*PP*VV];   // [n][t][p][v]  64 MB
__device__ float g_Ei[NB*VV*TT];
__device__ float g_Ej[NB*VV*TT];
__device__ float g_att[NB*TT*VV*VV];          // [n][t][i][j]  4 MB
__device__ float g_adjn[VV*VV];
__device__ float g_M[NB*TT*VV*VV];            // [n][t][v][j]  (TRANSPOSED) 4 MB

// ---------------- 1) 3x3 SAME conv (scalar fp32) ---------------------------
__global__ void __launch_bounds__(128) k_conv(const float* __restrict__ h,
                                              const float* __restrict__ cw,
                                              const float* __restrict__ cb) {
    __shared__ float sw[9*TT*TT];
    __shared__ float sb[TT];
    for (int i = threadIdx.x; i < 9*TT*TT; i += 128) sw[i] = cw[i];
    if (threadIdx.x < TT) sb[threadIdx.x] = cb[threadIdx.x];
    __syncthreads();

    const int v = threadIdx.x & 63;
    const int x = (blockIdx.x << 1) | (threadIdx.x >> 6);
    const int y = blockIdx.y;
    const int n = blockIdx.z;

    float acc[TT];
#pragma unroll
    for (int t = 0; t < TT; t++) acc[t] = sb[t];

    for (int dy = 0; dy < 3; dy++) {
        const int yy = y + dy - 1;
        if (yy < 0 || yy >= HH) continue;
        for (int dx = 0; dx < 3; dx++) {
            const int xx = x + dx - 1;
            if (xx < 0 || xx >= WW) continue;
            const float* hp = h + ((size_t)((n*HH + yy)*WW + xx) * TT) * VV + v;
            const float* wp = sw + (dy*3 + dx) * TT * TT;
#pragma unroll
            for (int ti = 0; ti < TT; ti++) {
                const float hv = hp[ti * VV];
#pragma unroll
                for (int to = 0; to < TT; to++)
                    acc[to] += hv * wp[ti*TT + to];
            }
        }
    }
    const int p = y*WW + x;
#pragma unroll
    for (int t = 0; t < TT; t++)
        g_Wt[((size_t)(n*TT + t) * PP + p) * VV + v] = acc[t];
}

// ---------------- 2) Ei / Ej reductions ------------------------------------
__global__ void __launch_bounds__(256) k_eij(const float* __restrict__ a) {
    __shared__ float sa[2*HH*WW];
    __shared__ float red[2][4][VV];
    for (int i = threadIdx.x; i < 2*HH*WW; i += 256) sa[i] = a[i];
    __syncthreads();

    const int v  = threadIdx.x & 63;
    const int q  = threadIdx.x >> 6;
    const int tp = blockIdx.x;
    const int n  = blockIdx.y;

    float ei = 0.f, ej = 0.f;
    for (int t = q*4; t < q*4 + 4; t++) {
        const float* wt = g_Wt + ((size_t)(n*TT + t) * PP + 2*tp*WW) * VV + v;
#pragma unroll 8
        for (int rw = 0; rw < 64; rw++) {
            const float xv = wt[rw * VV];
            const int r = rw >> 5, w = rw & 31;
            ei += xv * sa[(r*64 + w)      * 16 + t];
            ej += xv * sa[(r*64 + 32 + w) * 16 + t];
        }
    }
    red[0][q][v] = ei; red[1][q][v] = ej;
    __syncthreads();
    if (q == 0) {
        float si = red[0][0][v] + red[0][1][v] + red[0][2][v] + red[0][3][v];
        float sj = red[1][0][v] + red[1][1][v] + red[1][2][v] + red[1][3][v];
        g_Ei[(n*VV + v)*TT + tp] = si;
        g_Ej[(n*VV + v)*TT + tp] = sj;
    }
}

// ---------------- 3) adjacency normalization -------------------------------
__global__ void __launch_bounds__(64) k_adj(const float* __restrict__ B) {
    __shared__ float smin[VV], smax[VV], sd[VV];
    __shared__ float s_amin, s_ascale;
    const int i = threadIdx.x;
    float mn = 1e30f, mx = -1e30f;
    for (int j = 0; j < VV; j++) {
        float val = B[i*VV + j] + (i == j ? 1.f : 0.f);
        mn = fminf(mn, val); mx = fmaxf(mx, val);
    }
    smin[i] = mn; smax[i] = mx;
    __syncthreads();
    if (i == 0) {
        float a = 1e30f, b = -1e30f;
        for (int j = 0; j < VV; j++) { a = fminf(a, smin[j]); b = fmaxf(b, smax[j]); }
        s_amin = a; s_ascale = 1.f / (b - a);
    }
    __syncthreads();
    const float amin = s_amin, asc = s_ascale;
    float rs = 0.f;
    for (int j = 0; j < VV; j++)
        rs += (B[i*VV + j] + (i == j ? 1.f : 0.f) - amin) * asc;
    sd[i] = 1.f / sqrtf(rs);
    __syncthreads();
    const float di = sd[i];
    for (int j = 0; j < VV; j++) {
        float val = (B[i*VV + j] + (i == j ? 1.f : 0.f) - amin) * asc;
        g_adjn[i*VV + j] = val * di * sd[j];
    }
}

// ---------------- 4) leaky-relu + softmax over T ---------------------------
__global__ void __launch_bounds__(256) k_soft() {
    const int j  = threadIdx.x & 63;
    const int li = threadIdx.x >> 6;
    const int i  = blockIdx.x * 4 + li;
    const int n  = blockIdx.y;
    __shared__ float sEi[4][TT];
    if (j < TT) sEi[li][j] = g_Ei[(n*VV + i)*TT + j];
    __syncthreads();

    float e[TT];
    float mx = -1e30f;
#pragma unroll
    for (int t = 0; t < TT; t++) {
        float x = sEi[li][t] + g_Ej[(n*VV + j)*TT + t];
        x = (x > 0.f) ? x : LRELU_ALPHA * x;
        e[t] = x;
        mx = fmaxf(mx, x);
    }
    float s = 0.f;
#pragma unroll
    for (int t = 0; t < TT; t++) { e[t] = expf(e[t] - mx); s += e[t]; }
    const float inv = 1.f / s;
#pragma unroll
    for (int t = 0; t < TT; t++)
        g_att[((size_t)(n*TT + t)*VV + i)*VV + j] = e[t] * inv;
}

// ---------------- 5) M_T[n,t,v,j] = sum_i att[n,t,i,j] * adjn[i,v] ---------
__global__ void __launch_bounds__(256) k_M() {
    const int t = blockIdx.x, n = blockIdx.y;
    __shared__ float s_att[VV*VV];
    __shared__ float s_adj[VV*VV];
    const float* ap = g_att + (size_t)(n*TT + t) * VV * VV;
    for (int idx = threadIdx.x; idx < VV*VV; idx += 256) {
        s_att[idx] = ap[idx];
        s_adj[idx] = g_adjn[idx];
    }
    __syncthreads();
    const int j = threadIdx.x & 63, g = threadIdx.x >> 6;
    float* mp = g_M + (size_t)(n*TT + t) * VV * VV;
    for (int v = g*16; v < g*16 + 16; v++) {
        float acc = 0.f;
#pragma unroll
        for (int i = 0; i < VV; i++)
            acc += s_att[i*VV + j] * s_adj[i*VV + v];
        mp[v*VV + j] = acc;      // transposed: [v][j]
    }
}

// ---------------- 6) k_out via mma.sync bf16 split-precision ---------------
// out[n,p,t,v] = elu( sum_j Wt[n,t,p,j] * M_T[n,t,v,j] )
// Per CTA (128 thr, 4 warps): one (n, t, 128-row p-tile). M=128,N=64,K=64.
// 3 passes: Ah*Bh + Al*Bh + Ah*Bl, fp32 accum (HMMA m16n8k16).
#define ASTR 72                     // bf16 row stride (144B) -> conflict-free frags
#define OFF_AH 0
#define OFF_AL (128*ASTR)
#define OFF_BH (2*128*ASTR)
#define OFF_BL (2*128*ASTR + 64*ASTR)
#define SMEM_ELEMS (2*128*ASTR + 2*64*ASTR)

__device__ __forceinline__ void mma16816(float c[4], uint32_t a0, uint32_t a1,
                                         uint32_t a2, uint32_t a3,
                                         uint32_t b0, uint32_t b1) {
    asm volatile(
        "mma.sync.aligned.m16n8k16.row.col.f32.bf16.bf16.f32 "
        "{%0,%1,%2,%3}, {%4,%5,%6,%7}, {%8,%9}, {%0,%1,%2,%3};"
        : "+f"(c[0]), "+f"(c[1]), "+f"(c[2]), "+f"(c[3])
        : "r"(a0), "r"(a1), "r"(a2), "r"(a3), "r"(b0), "r"(b1));
}

__global__ void __launch_bounds__(128) k_out_m(float* __restrict__ out) {
    extern __shared__ __nv_bfloat16 sm[];
    const int tid = threadIdx.x;
    const int wid = tid >> 5, lane = tid & 31;
    const int g = lane >> 2, tg = lane & 3;

    const int pt = blockIdx.x;       // 0..7
    const int t  = blockIdx.y;
    const int n  = blockIdx.z;

    // ---- stage A (128x64) and B (64x64) as bf16 hi/lo ----
    const float* wp = g_Wt + ((size_t)(n*TT + t) * PP + pt*128) * VV;
    const float* mp = g_M  + (size_t)(n*TT + t) * VV * VV;
    for (int idx = tid; idx < 128*32; idx += 128) {
        const int row = idx >> 5, cp = idx & 31;
        const float2 x = *reinterpret_cast<const float2*>(wp + row*VV + cp*2);
        __nv_bfloat16 h0 = __float2bfloat16(x.x), h1 = __float2bfloat16(x.y);
        __nv_bfloat16 l0 = __float2bfloat16(x.x - __bfloat162float(h0));
        __nv_bfloat16 l1 = __float2bfloat16(x.y - __bfloat162float(h1));
        *reinterpret_cast<__nv_bfloat162*>(&sm[OFF_AH + row*ASTR + cp*2]) = __nv_bfloat162(h0, h1);
        *reinterpret_cast<__nv_bfloat162*>(&sm[OFF_AL + row*ASTR + cp*2]) = __nv_bfloat162(l0, l1);
    }
    for (int idx = tid; idx < 64*32; idx += 128) {
        const int row = idx >> 5, cp = idx & 31;
        const float2 x = *reinterpret_cast<const float2*>(mp + row*VV + cp*2);
        __nv_bfloat16 h0 = __float2bfloat16(x.x), h1 = __float2bfloat16(x.y);
        __nv_bfloat16 l0 = __float2bfloat16(x.x - __bfloat162float(h0));
        __nv_bfloat16 l1 = __float2bfloat16(x.y - __bfloat162float(h1));
        *reinterpret_cast<__nv_bfloat162*>(&sm[OFF_BH + row*ASTR + cp*2]) = __nv_bfloat162(h0, h1);
        *reinterpret_cast<__nv_bfloat162*>(&sm[OFF_BL + row*ASTR + cp*2]) = __nv_bfloat162(l0, l1);
    }
    __syncthreads();

    const int mbase = wid*32;
    float acc[2][8][4];
#pragma unroll
    for (int mt = 0; mt < 2; mt++)
#pragma unroll
        for (int nt = 0; nt < 8; nt++)
#pragma unroll
            for (int c = 0; c < 4; c++) acc[mt][nt][c] = 0.f;

#pragma unroll
    for (int pass = 0; pass < 3; pass++) {
        const int aoff = (pass == 1) ? OFF_AL : OFF_AH;
        const int boff = (pass == 2) ? OFF_BL : OFF_BH;

        // A fragments: a[mt][ks][0..3]
        uint32_t afrag[2][4][4];
#pragma unroll
        for (int mt = 0; mt < 2; mt++) {
            const int r0 = mbase + mt*16 + g;
#pragma unroll
            for (int ks = 0; ks < 4; ks++) {
                const int c0 = ks*16 + tg*2;
                afrag[mt][ks][0] = *reinterpret_cast<const uint32_t*>(&sm[aoff + r0*ASTR + c0]);
                afrag[mt][ks][1] = *reinterpret_cast<const uint32_t*>(&sm[aoff + (r0+8)*ASTR + c0]);
                afrag[mt][ks][2] = *reinterpret_cast<const uint32_t*>(&sm[aoff + r0*ASTR + c0 + 8]);
                afrag[mt][ks][3] = *reinterpret_cast<const uint32_t*>(&sm[aoff + (r0+8)*ASTR + c0 + 8]);
            }
        }
#pragma unroll
        for (int nt = 0; nt < 8; nt++) {
            const int br = nt*8 + g;
#pragma unroll
            for (int ks = 0; ks < 4; ks++) {
                const int c0 = ks*16 + tg*2;
                const uint32_t b0 = *reinterpret_cast<const uint32_t*>(&sm[boff + br*ASTR + c0]);
                const uint32_t b1 = *reinterpret_cast<const uint32_t*>(&sm[boff + br*ASTR + c0 + 8]);
#pragma unroll
                for (int mt = 0; mt < 2; mt++)
                    mma16816(acc[mt][nt], afrag[mt][ks][0], afrag[mt][ks][1],
                             afrag[mt][ks][2], afrag[mt][ks][3], b0, b1);
            }
        }
    }

    // ---- epilogue: ELU + store ----
    // C[g + mt*16 + mbase][nt*8 + tg*2 (+1)] rows g and g+8
#pragma unroll
    for (int mt = 0; mt < 2; mt++) {
        const int p0 = pt*128 + mbase + mt*16 + g;
#pragma unroll
        for (int nt = 0; nt < 8; nt++) {
            const int v0 = nt*8 + tg*2;
            float x0 = acc[mt][nt][0], x1 = acc[mt][nt][1];
            float x2 = acc[mt][nt][2], x3 = acc[mt][nt][3];
            float2 r0, r1;
            r0.x = (x0 > 0.f) ? x0 : expm1f(x0);
            r0.y = (x1 > 0.f) ? x1 : expm1f(x1);
            r1.x = (x2 > 0.f) ? x2 : expm1f(x2);
            r1.y = (x3 > 0.f) ? x3 : expm1f(x3);
            *reinterpret_cast<float2*>(out + (((size_t)(n*PP + p0))   * TT + t) * VV + v0) = r0;
            *reinterpret_cast<float2*>(out + (((size_t)(n*PP + p0+8)) * TT + t) * VV + v0) = r1;
        }
    }
}

// ---------------------------------------------------------------------------
extern "C" void kernel_launch(void* const* d_in, const int* in_sizes, int n_in,
                              void* d_out, int out_size) {
    const float* h  = (const float*)d_in[0];   // (16,32,32,16,64)
    const float* cw = (const float*)d_in[1];   // (3,3,16,16)
    const float* cb = (const float*)d_in[2];   // (16,)
    const float* a  = (const float*)d_in[3];   // (2048,1)
    const float* B  = (const float*)d_in[4];   // (64,64)
    float* out = (float*)d_out;

    static int smem_set = 0;
    if (!smem_set) {
        cudaFuncSetAttribute(k_out_m, cudaFuncAttributeMaxDynamicSharedMemorySize,
                             SMEM_ELEMS * (int)sizeof(__nv_bfloat16));
        smem_set = 1;
    }

    k_conv<<<dim3(WW/2, HH, NB), 128>>>(h, cw, cb);
    k_adj<<<1, 64>>>(B);
    k_eij<<<dim3(TT, NB), 256>>>(a);
    k_soft<<<dim3(VV/4, NB), 256>>>();
    k_M<<<dim3(TT, NB), 256>>>();
    k_out_m<<<dim3(8, TT, NB), 128, SMEM_ELEMS * (int)sizeof(__nv_bfloat16)>>>(out);
}